// round 12
// baseline (speedup 1.0000x reference)
#include <cuda_runtime.h>
#include <math_constants.h>
#include <cstdint>

// DotAttention: context[b,f] = softmax_t(<hd[b],he[b,t]>) . he[b,t,f]
// b=64, t=2048, f=1024, fp32.
// Partial: per-warp 3-stage cp.async pipeline, SPLITS=4 -> 256 CTAs =
// one full wave (no wave-2 tail), half the epilogues, half the g_ctx traffic.
// Combine: 4-term reduction, launched with PDL to overlap the partial tail.

#define BB 64
#define TT 2048
#define FF 1024
#define SPLITS 4
#define TCHUNK (TT / SPLITS)             // 512 rows per CTA
#define NWARPS 8
#define ROWS_PER_WARP (TCHUNK / NWARPS)  // 64
#define STAGES 3
#define ROW_BYTES (FF * 4)               // 4096 B per row
#define SMEM_BYTES (NWARPS * STAGES * ROW_BYTES)  // 98304

// scratch (allocation-free)
__device__ float g_ctx[(size_t)BB * SPLITS * FF];   // 1 MB
__device__ float g_m[BB * SPLITS];
__device__ float g_l[BB * SPLITS];

#define CP_ASYNC16(dst, src) \
    asm volatile("cp.async.cg.shared.global [%0], [%1], 16;" \
                 :: "r"(dst), "l"(src) : "memory")
#define CP_COMMIT() asm volatile("cp.async.commit_group;" ::: "memory")
#define CP_WAIT2()  asm volatile("cp.async.wait_group 2;" ::: "memory")
#define CP_WAIT0()  asm volatile("cp.async.wait_group 0;" ::: "memory")

__device__ __forceinline__ unsigned int smem_u32(const void* p) {
    unsigned int a;
    asm("{ .reg .u64 t; cvta.to.shared.u64 t, %1; cvt.u32.u64 %0, t; }"
        : "=r"(a) : "l"(p));
    return a;
}

__global__ __launch_bounds__(256)
void attn_partial_kernel(const float* __restrict__ hd,
                         const float* __restrict__ he) {
    extern __shared__ char smem_raw[];   // SMEM_BYTES
    const int s    = blockIdx.x;         // t-split
    const int b    = blockIdx.y;         // batch
    const int warp = threadIdx.x >> 5;
    const int lane = threadIdx.x & 31;

    // per-warp private stage base; lane offset folded in
    const unsigned int sbase = smem_u32(smem_raw)
                             + warp * (STAGES * ROW_BYTES) + lane * 16;

    // q: 32 floats per lane, lane-major so loads are coalesced.
    const float4* q4 = reinterpret_cast<const float4*>(hd + (size_t)b * FF);
    float4 q[8];
#pragma unroll
    for (int j = 0; j < 8; j++) q[j] = q4[j * 32 + lane];

    float  m = -CUDART_INF_F;
    float  l = 0.0f;
    float4 acc[8];
#pragma unroll
    for (int j = 0; j < 8; j++) acc[j] = make_float4(0.f, 0.f, 0.f, 0.f);

    const int t_base = s * TCHUNK + warp;

    // ---- prologue: prefetch rows 0..2 into stages 0..2 ----
#pragma unroll
    for (int st = 0; st < STAGES; st++) {
        const int t = t_base + st * NWARPS;
        const float4* src = reinterpret_cast<const float4*>(
            he + ((size_t)b * TT + t) * FF);
        const unsigned int dst = sbase + st * ROW_BYTES;
#pragma unroll
        for (int j = 0; j < 8; j++)
            CP_ASYNC16(dst + j * 512, src + j * 32 + lane);
        CP_COMMIT();
    }

    int stage = 0;
    for (int r = 0; r < ROWS_PER_WARP; r++) {
        if (r >= ROWS_PER_WARP - STAGES) { CP_WAIT0(); } else { CP_WAIT2(); }

        const unsigned int stg = sbase + stage * ROW_BYTES;

        // row into registers from smem (conflict-free LDS.128)
        float4 v[8];
#pragma unroll
        for (int j = 0; j < 8; j++) {
            asm volatile("ld.shared.v4.f32 {%0,%1,%2,%3}, [%4];"
                         : "=f"(v[j].x), "=f"(v[j].y),
                           "=f"(v[j].z), "=f"(v[j].w)
                         : "r"(stg + j * 512));
        }

        // prefetch row r+STAGES into the just-consumed stage, BEFORE compute:
        // the loads overlap the dot/shfl/exp/accumulate chain below.
        if (r + STAGES < ROWS_PER_WARP) {
            const int t2 = t_base + (r + STAGES) * NWARPS;
            const float4* src = reinterpret_cast<const float4*>(
                he + ((size_t)b * TT + t2) * FF);
#pragma unroll
            for (int j = 0; j < 8; j++)
                CP_ASYNC16(stg + j * 512, src + j * 32 + lane);
            CP_COMMIT();
        }

        // dot(q, v): 4 independent accumulator chains
        float d0 = 0.f, d1 = 0.f, d2 = 0.f, d3 = 0.f;
#pragma unroll
        for (int j = 0; j < 8; j++) {
            d0 += v[j].x * q[j].x;
            d1 += v[j].y * q[j].y;
            d2 += v[j].z * q[j].z;
            d3 += v[j].w * q[j].w;
        }
        float d = (d0 + d1) + (d2 + d3);
#pragma unroll
        for (int off = 16; off; off >>= 1)
            d += __shfl_xor_sync(0xffffffffu, d, off);
        // d is warp-uniform -> uniform branch below (no divergence)

        if (d <= m) {
            const float p = __expf(d - m);
            l += p;
#pragma unroll
            for (int j = 0; j < 8; j++) {
                acc[j].x += p * v[j].x;
                acc[j].y += p * v[j].y;
                acc[j].z += p * v[j].z;
                acc[j].w += p * v[j].w;
            }
        } else {
            const float sc = __expf(m - d);   // 0 on first row (m = -inf)
            m = d;
            l = l * sc + 1.0f;                // p = exp(d - d) = 1
#pragma unroll
            for (int j = 0; j < 8; j++) {
                acc[j].x = acc[j].x * sc + v[j].x;
                acc[j].y = acc[j].y * sc + v[j].y;
                acc[j].z = acc[j].z * sc + v[j].z;
                acc[j].w = acc[j].w * sc + v[j].w;
            }
        }

        stage = (stage + 1 == STAGES) ? 0 : stage + 1;
    }

    // ---- combine the 8 warps of this CTA ----
    __shared__ float s_m[NWARPS];
    __shared__ float s_l[NWARPS];
    float* s_ctx = reinterpret_cast<float*>(smem_raw);  // alias stages

    __syncthreads();   // all warps done with their stage buffers
    for (int i = threadIdx.x; i < FF; i += 256) s_ctx[i] = 0.0f;
    if (lane == 0) { s_m[warp] = m; s_l[warp] = l; }
    __syncthreads();

    float M = s_m[0];
#pragma unroll
    for (int w = 1; w < NWARPS; w++) M = fmaxf(M, s_m[w]);

    const float sc = __expf(m - M);
#pragma unroll
    for (int j = 0; j < 8; j++) {
        const int f = (j * 32 + lane) * 4;
        atomicAdd(&s_ctx[f + 0], acc[j].x * sc);
        atomicAdd(&s_ctx[f + 1], acc[j].y * sc);
        atomicAdd(&s_ctx[f + 2], acc[j].z * sc);
        atomicAdd(&s_ctx[f + 3], acc[j].w * sc);
    }
    __syncthreads();

    const int chunk = b * SPLITS + s;
    if (threadIdx.x == 0) {
        float L = 0.0f;
#pragma unroll
        for (int w = 0; w < NWARPS; w++) L += s_l[w] * __expf(s_m[w] - M);
        g_m[chunk] = M;
        g_l[chunk] = L;
    }
    float* outp = g_ctx + (size_t)chunk * FF;
    for (int i = threadIdx.x; i < FF; i += 256) outp[i] = s_ctx[i];
}

// grid = (FF/128, BB), 128 threads: one output element per thread.
// PDL: launched alongside the partial; waits on grid dependency before
// touching the partial's outputs.
__global__ __launch_bounds__(128)
void attn_combine_kernel(float* __restrict__ out) {
    const int b = blockIdx.y;
    const int f = blockIdx.x * 128 + threadIdx.x;

    cudaGridDependencySynchronize();   // partial grid fully done

    float M = -CUDART_INF_F;
#pragma unroll
    for (int s = 0; s < SPLITS; s++) M = fmaxf(M, g_m[b * SPLITS + s]);

    float L = 0.0f;
    float v = 0.0f;
#pragma unroll
    for (int s = 0; s < SPLITS; s++) {
        const float e = __expf(g_m[b * SPLITS + s] - M);
        L += g_l[b * SPLITS + s] * e;
        v += g_ctx[((size_t)b * SPLITS + s) * FF + f] * e;
    }
    out[(size_t)b * FF + f] = v / L;
}

extern "C" void kernel_launch(void* const* d_in, const int* in_sizes, int n_in,
                              void* d_out, int out_size) {
    const float* hd = (const float*)d_in[0];   // (64, 1024)
    const float* he = (const float*)d_in[1];   // (64, 2048, 1024)
    float* out = (float*)d_out;                // (64, 1024)
    (void)in_sizes; (void)n_in; (void)out_size;

    static int attr_set = 0;
    if (!attr_set) {
        cudaFuncSetAttribute(attn_partial_kernel,
                             cudaFuncAttributeMaxDynamicSharedMemorySize,
                             SMEM_BYTES);
        attr_set = 1;
    }

    dim3 grid(SPLITS, BB);
    attn_partial_kernel<<<grid, 256, SMEM_BYTES>>>(hd, he);

    // combine with programmatic dependent launch (overlaps partial tail)
    cudaLaunchConfig_t cfg = {};
    cfg.gridDim  = dim3(FF / 128, BB);
    cfg.blockDim = dim3(128);
    cudaLaunchAttribute attrs[1];
    attrs[0].id = cudaLaunchAttributeProgrammaticStreamSerialization;
    attrs[0].val.programmaticStreamSerializationAllowed = 1;
    cfg.attrs = attrs;
    cfg.numAttrs = 1;
    cudaLaunchKernelEx(&cfg, attn_combine_kernel, out);
}

// round 14
// speedup vs baseline: 1.0295x; 1.0295x over previous
#include <cuda_runtime.h>
#include <math_constants.h>
#include <cstdint>

// DotAttention: context[b,f] = softmax_t(<hd[b],he[b,t]>) . he[b,t,f]
// b=64, t=2048, f=1024, fp32.
// R13 = R11 (best, 88.5us) with the CTA epilogue's 8192 smem atomics
// replaced by store + tree-reduce in the dead pipeline-stage smem.

#define BB 64
#define TT 2048
#define FF 1024
#define SPLITS 8
#define TCHUNK (TT / SPLITS)             // 256 rows per CTA
#define NWARPS 8
#define ROWS_PER_WARP (TCHUNK / NWARPS)  // 32
#define STAGES 3
#define ROW_BYTES (FF * 4)               // 4096 B per row
#define SMEM_BYTES (NWARPS * STAGES * ROW_BYTES)  // 98304

// scratch (allocation-free)
__device__ float g_ctx[(size_t)BB * SPLITS * FF];   // 2 MB
__device__ float g_m[BB * SPLITS];
__device__ float g_l[BB * SPLITS];

#define CP_ASYNC16(dst, src) \
    asm volatile("cp.async.cg.shared.global [%0], [%1], 16;" \
                 :: "r"(dst), "l"(src) : "memory")
#define CP_COMMIT() asm volatile("cp.async.commit_group;" ::: "memory")
#define CP_WAIT2()  asm volatile("cp.async.wait_group 2;" ::: "memory")
#define CP_WAIT0()  asm volatile("cp.async.wait_group 0;" ::: "memory")

__device__ __forceinline__ unsigned int smem_u32(const void* p) {
    unsigned int a;
    asm("{ .reg .u64 t; cvta.to.shared.u64 t, %1; cvt.u32.u64 %0, t; }"
        : "=r"(a) : "l"(p));
    return a;
}

__global__ __launch_bounds__(256)
void attn_partial_kernel(const float* __restrict__ hd,
                         const float* __restrict__ he) {
    extern __shared__ char smem_raw[];   // SMEM_BYTES
    const int s    = blockIdx.x;         // t-split
    const int b    = blockIdx.y;         // batch
    const int warp = threadIdx.x >> 5;
    const int lane = threadIdx.x & 31;

    // per-warp private stage base; lane offset folded in
    const unsigned int sbase = smem_u32(smem_raw)
                             + warp * (STAGES * ROW_BYTES) + lane * 16;

    // q: 32 floats per lane, lane-major so loads are coalesced.
    const float4* q4 = reinterpret_cast<const float4*>(hd + (size_t)b * FF);
    float4 q[8];
#pragma unroll
    for (int j = 0; j < 8; j++) q[j] = q4[j * 32 + lane];

    float  m = -CUDART_INF_F;
    float  l = 0.0f;
    float4 acc[8];
#pragma unroll
    for (int j = 0; j < 8; j++) acc[j] = make_float4(0.f, 0.f, 0.f, 0.f);

    const int t_base = s * TCHUNK + warp;

    // ---- prologue: prefetch rows 0..2 into stages 0..2 ----
#pragma unroll
    for (int st = 0; st < STAGES; st++) {
        const int t = t_base + st * NWARPS;
        const float4* src = reinterpret_cast<const float4*>(
            he + ((size_t)b * TT + t) * FF);
        const unsigned int dst = sbase + st * ROW_BYTES;
#pragma unroll
        for (int j = 0; j < 8; j++)
            CP_ASYNC16(dst + j * 512, src + j * 32 + lane);
        CP_COMMIT();
    }

    int stage = 0;
    for (int r = 0; r < ROWS_PER_WARP; r++) {
        if (r >= ROWS_PER_WARP - STAGES) { CP_WAIT0(); } else { CP_WAIT2(); }

        const unsigned int stg = sbase + stage * ROW_BYTES;

        // row into registers from smem (conflict-free LDS.128)
        float4 v[8];
#pragma unroll
        for (int j = 0; j < 8; j++) {
            asm volatile("ld.shared.v4.f32 {%0,%1,%2,%3}, [%4];"
                         : "=f"(v[j].x), "=f"(v[j].y),
                           "=f"(v[j].z), "=f"(v[j].w)
                         : "r"(stg + j * 512));
        }

        // prefetch row r+STAGES into the just-consumed stage, BEFORE compute:
        // the loads overlap the dot/shfl/exp/accumulate chain below.
        if (r + STAGES < ROWS_PER_WARP) {
            const int t2 = t_base + (r + STAGES) * NWARPS;
            const float4* src = reinterpret_cast<const float4*>(
                he + ((size_t)b * TT + t2) * FF);
#pragma unroll
            for (int j = 0; j < 8; j++)
                CP_ASYNC16(stg + j * 512, src + j * 32 + lane);
            CP_COMMIT();
        }

        // dot(q, v): 4 independent accumulator chains
        float d0 = 0.f, d1 = 0.f, d2 = 0.f, d3 = 0.f;
#pragma unroll
        for (int j = 0; j < 8; j++) {
            d0 += v[j].x * q[j].x;
            d1 += v[j].y * q[j].y;
            d2 += v[j].z * q[j].z;
            d3 += v[j].w * q[j].w;
        }
        float d = (d0 + d1) + (d2 + d3);
#pragma unroll
        for (int off = 16; off; off >>= 1)
            d += __shfl_xor_sync(0xffffffffu, d, off);
        // d is warp-uniform -> uniform branch below (no divergence)

        if (d <= m) {
            const float p = __expf(d - m);
            l += p;
#pragma unroll
            for (int j = 0; j < 8; j++) {
                acc[j].x += p * v[j].x;
                acc[j].y += p * v[j].y;
                acc[j].z += p * v[j].z;
                acc[j].w += p * v[j].w;
            }
        } else {
            const float sc = __expf(m - d);   // 0 on first row (m = -inf)
            m = d;
            l = l * sc + 1.0f;                // p = exp(d - d) = 1
#pragma unroll
            for (int j = 0; j < 8; j++) {
                acc[j].x = acc[j].x * sc + v[j].x;
                acc[j].y = acc[j].y * sc + v[j].y;
                acc[j].z = acc[j].z * sc + v[j].z;
                acc[j].w = acc[j].w * sc + v[j].w;
            }
        }

        stage = (stage + 1 == STAGES) ? 0 : stage + 1;
    }

    // ---- combine the 8 warps of this CTA (no atomics) ----
    __shared__ float s_m[NWARPS];
    __shared__ float s_l[NWARPS];
    // reuse dead stage smem: 8 rows x 1024 floats = 32KB
    float* s_red = reinterpret_cast<float*>(smem_raw);

    if (lane == 0) { s_m[warp] = m; s_l[warp] = l; }
    __syncthreads();   // stages dead; s_m/s_l visible

    float M = s_m[0];
#pragma unroll
    for (int w = 1; w < NWARPS; w++) M = fmaxf(M, s_m[w]);

    // each warp stores its rescaled accumulator row (conflict-free STS.128)
    const float sc = __expf(m - M);
    float4* myrow = reinterpret_cast<float4*>(s_red + warp * FF);
#pragma unroll
    for (int j = 0; j < 8; j++) {
        float4 a = acc[j];
        a.x *= sc; a.y *= sc; a.z *= sc; a.w *= sc;
        myrow[j * 32 + lane] = a;
    }
    __syncthreads();

    const int chunk = b * SPLITS + s;
    if (threadIdx.x == 0) {
        float L = 0.0f;
#pragma unroll
        for (int w = 0; w < NWARPS; w++) L += s_l[w] * __expf(s_m[w] - M);
        g_m[chunk] = M;
        g_l[chunk] = L;
    }

    // tree-reduce: each thread owns one float4 column slice (tid = 0..255)
    {
        const int i = threadIdx.x;            // float4 index 0..255
        const float4* r4 = reinterpret_cast<const float4*>(s_red);
        float4 sum = r4[i];                   // warp 0 row
#pragma unroll
        for (int w = 1; w < NWARPS; w++) {
            float4 a = r4[w * (FF / 4) + i];
            sum.x += a.x; sum.y += a.y; sum.z += a.z; sum.w += a.w;
        }
        reinterpret_cast<float4*>(g_ctx + (size_t)chunk * FF)[i] = sum;
    }
}

// grid = (FF/128, BB), 128 threads: one output element per thread (best-known).
__global__ __launch_bounds__(128)
void attn_combine_kernel(float* __restrict__ out) {
    const int b = blockIdx.y;
    const int f = blockIdx.x * 128 + threadIdx.x;

    float M = -CUDART_INF_F;
#pragma unroll
    for (int s = 0; s < SPLITS; s++) M = fmaxf(M, g_m[b * SPLITS + s]);

    float L = 0.0f;
    float v = 0.0f;
#pragma unroll
    for (int s = 0; s < SPLITS; s++) {
        const float e = __expf(g_m[b * SPLITS + s] - M);
        L += g_l[b * SPLITS + s] * e;
        v += g_ctx[((size_t)b * SPLITS + s) * FF + f] * e;
    }
    out[(size_t)b * FF + f] = v / L;
}

extern "C" void kernel_launch(void* const* d_in, const int* in_sizes, int n_in,
                              void* d_out, int out_size) {
    const float* hd = (const float*)d_in[0];   // (64, 1024)
    const float* he = (const float*)d_in[1];   // (64, 2048, 1024)
    float* out = (float*)d_out;                // (64, 1024)
    (void)in_sizes; (void)n_in; (void)out_size;

    static int attr_set = 0;
    if (!attr_set) {
        cudaFuncSetAttribute(attn_partial_kernel,
                             cudaFuncAttributeMaxDynamicSharedMemorySize,
                             SMEM_BYTES);
        attr_set = 1;
    }

    dim3 grid(SPLITS, BB);
    attn_partial_kernel<<<grid, 256, SMEM_BYTES>>>(hd, he);

    dim3 cgrid(FF / 128, BB);
    attn_combine_kernel<<<cgrid, 128>>>(out);
}